// round 1
// baseline (speedup 1.0000x reference)
#include <cuda_runtime.h>
#include <math.h>

#define S   8192
#define CC  512
#define NHW 1024
#define BM  64
#define BN  64
#define BK  16

// Scratch (allocation-free rule: __device__ globals)
__device__ float g_a[S * CC];
__device__ float g_b[S * CC];
__device__ float g_c[S * CC];
__device__ float g_k[S * CC];
__device__ float g_v[S * CC];
__device__ float g_scores[(size_t)S * S];

// ---------------------------------------------------------------------------
// rmsnorm (+ optional silu): one block per token, 256 threads, 2 elems/thread
// y = x * sqrt(C) / (||x|| + 1e-8) * gamma ; silu(v) = v * sigmoid(v)
// ---------------------------------------------------------------------------
__global__ __launch_bounds__(256) void rmsnorm_kernel(
    const float* __restrict__ X, const float* __restrict__ g,
    float* __restrict__ out, int dosilu)
{
    int m = blockIdx.x;
    const float* xr = X + (size_t)m * CC;
    float* orow = out + (size_t)m * CC;
    int tid = threadIdx.x;
    float x0 = xr[tid], x1 = xr[tid + 256];
    __shared__ float red[256];
    red[tid] = x0 * x0 + x1 * x1;
    __syncthreads();
    for (int s = 128; s > 0; s >>= 1) {
        if (tid < s) red[tid] += red[tid + s];
        __syncthreads();
    }
    float scale = 22.627416997969522f / (sqrtf(red[0]) + 1e-8f);
    float y0 = x0 * scale * g[tid];
    float y1 = x1 * scale * g[tid + 256];
    if (dosilu) {
        y0 = y0 / (1.0f + __expf(-y0));
        y1 = y1 / (1.0f + __expf(-y1));
    }
    orow[tid] = y0;
    orow[tid + 256] = y1;
}

// ---------------------------------------------------------------------------
// Conv-as-GEMM: out[m, n] = sum_tap sum_k A[src(m,tap), k] * W[tap, k, n] + bias[n] (+res)
// ntaps = 27 (3x3x3 causal conv with edge padding) or 1 (1x1 conv / matmul).
// 64x64 block tile, 4x4 thread tile, BK=16, 256 threads.
// ---------------------------------------------------------------------------
__global__ __launch_bounds__(256) void gemm_conv_kernel(
    const float* __restrict__ A, const float* __restrict__ W,
    const float* __restrict__ bias, const float* __restrict__ res,
    float* __restrict__ out, int ntaps)
{
    __shared__ float As[BK][BM + 4];
    __shared__ float Bs[BK][BN + 4];
    int tid = threadIdx.x;
    int m0 = blockIdx.x * BM;
    int n0 = blockIdx.y * BN;
    int ty = tid >> 4, tx = tid & 15;
    int la_r = tid >> 2, la_c = (tid & 3) * 4;   // A loader: 64 rows x 4 float4-groups
    int lb_r = tid >> 4, lb_c = (tid & 15) * 4;  // B loader: 16 rows x 16 float4-groups

    int m = m0 + la_r;
    int t = m >> 10, y = (m >> 5) & 31, x = m & 31;

    float acc[4][4] = {{0.f,0.f,0.f,0.f},{0.f,0.f,0.f,0.f},{0.f,0.f,0.f,0.f},{0.f,0.f,0.f,0.f}};

    for (int tap = 0; tap < ntaps; ++tap) {
        int src;
        if (ntaps == 1) {
            src = m;
        } else {
            int dt = tap / 9, dy = (tap / 3) % 3, dx = tap % 3;
            int st = t + dt - 2; st = st < 0 ? 0 : st;
            int sy = y + dy - 1; sy = sy < 0 ? 0 : (sy > 31 ? 31 : sy);
            int sx = x + dx - 1; sx = sx < 0 ? 0 : (sx > 31 ? 31 : sx);
            src = (st << 10) + (sy << 5) + sx;
        }
        const float* a_ptr = A + (size_t)src * CC + la_c;
        const float* b_ptr = W + (size_t)tap * CC * CC + (size_t)lb_r * CC + n0 + lb_c;

        for (int kc = 0; kc < CC; kc += BK) {
            float4 av = *(const float4*)(a_ptr + kc);
            float4 bv = *(const float4*)(b_ptr + (size_t)kc * CC);
            As[la_c + 0][la_r] = av.x;
            As[la_c + 1][la_r] = av.y;
            As[la_c + 2][la_r] = av.z;
            As[la_c + 3][la_r] = av.w;
            *(float4*)&Bs[lb_r][lb_c] = bv;
            __syncthreads();
#pragma unroll
            for (int k = 0; k < BK; ++k) {
                float4 a = *(const float4*)&As[k][ty * 4];
                float4 b = *(const float4*)&Bs[k][tx * 4];
                acc[0][0] += a.x * b.x; acc[0][1] += a.x * b.y; acc[0][2] += a.x * b.z; acc[0][3] += a.x * b.w;
                acc[1][0] += a.y * b.x; acc[1][1] += a.y * b.y; acc[1][2] += a.y * b.z; acc[1][3] += a.y * b.w;
                acc[2][0] += a.z * b.x; acc[2][1] += a.z * b.y; acc[2][2] += a.z * b.z; acc[2][3] += a.z * b.w;
                acc[3][0] += a.w * b.x; acc[3][1] += a.w * b.y; acc[3][2] += a.w * b.z; acc[3][3] += a.w * b.w;
            }
            __syncthreads();
        }
    }

    int nn = n0 + tx * 4;
    float4 bia = *(const float4*)&bias[nn];
#pragma unroll
    for (int i = 0; i < 4; ++i) {
        int mm = m0 + ty * 4 + i;
        float4 o;
        o.x = acc[i][0] + bia.x;
        o.y = acc[i][1] + bia.y;
        o.z = acc[i][2] + bia.z;
        o.w = acc[i][3] + bia.w;
        if (res) {
            float4 r = *(const float4*)&res[(size_t)mm * CC + nn];
            o.x += r.x; o.y += r.y; o.z += r.z; o.w += r.w;
        }
        *(float4*)&out[(size_t)mm * CC + nn] = o;
    }
}

// ---------------------------------------------------------------------------
// QK^T: Sc[q, k] = scale * sum_c Q[q, c] * K[k, c], only frame(k) <= frame(q)
// ---------------------------------------------------------------------------
__global__ __launch_bounds__(256) void gemm_qk_kernel(
    const float* __restrict__ Q, const float* __restrict__ Km,
    float* __restrict__ Sc)
{
    int q0 = blockIdx.x * BM;
    int k0 = blockIdx.y * BN;
    if ((k0 / NHW) > (q0 / NHW)) return;

    __shared__ float As[BK][BM + 4];
    __shared__ float Bs[BK][BN + 4];
    int tid = threadIdx.x;
    int ty = tid >> 4, tx = tid & 15;
    int l_r = tid >> 2, l_c = (tid & 3) * 4;

    const float* a_ptr = Q  + (size_t)(q0 + l_r) * CC + l_c;
    const float* b_ptr = Km + (size_t)(k0 + l_r) * CC + l_c;

    float acc[4][4] = {{0.f,0.f,0.f,0.f},{0.f,0.f,0.f,0.f},{0.f,0.f,0.f,0.f},{0.f,0.f,0.f,0.f}};

    for (int kc = 0; kc < CC; kc += BK) {
        float4 av = *(const float4*)(a_ptr + kc);
        float4 bv = *(const float4*)(b_ptr + kc);
        As[l_c + 0][l_r] = av.x; As[l_c + 1][l_r] = av.y;
        As[l_c + 2][l_r] = av.z; As[l_c + 3][l_r] = av.w;
        Bs[l_c + 0][l_r] = bv.x; Bs[l_c + 1][l_r] = bv.y;
        Bs[l_c + 2][l_r] = bv.z; Bs[l_c + 3][l_r] = bv.w;
        __syncthreads();
#pragma unroll
        for (int k = 0; k < BK; ++k) {
            float4 a = *(const float4*)&As[k][ty * 4];
            float4 b = *(const float4*)&Bs[k][tx * 4];
            acc[0][0] += a.x * b.x; acc[0][1] += a.x * b.y; acc[0][2] += a.x * b.z; acc[0][3] += a.x * b.w;
            acc[1][0] += a.y * b.x; acc[1][1] += a.y * b.y; acc[1][2] += a.y * b.z; acc[1][3] += a.y * b.w;
            acc[2][0] += a.z * b.x; acc[2][1] += a.z * b.y; acc[2][2] += a.z * b.z; acc[2][3] += a.z * b.w;
            acc[3][0] += a.w * b.x; acc[3][1] += a.w * b.y; acc[3][2] += a.w * b.z; acc[3][3] += a.w * b.w;
        }
        __syncthreads();
    }

    const float scale = 0.044194173824159216f;  // 1/sqrt(512)
#pragma unroll
    for (int i = 0; i < 4; ++i) {
        float4 o;
        o.x = acc[i][0] * scale; o.y = acc[i][1] * scale;
        o.z = acc[i][2] * scale; o.w = acc[i][3] * scale;
        *(float4*)&Sc[(size_t)(q0 + ty * 4 + i) * S + (k0 + tx * 4)] = o;
    }
}

// ---------------------------------------------------------------------------
// Row softmax over valid length L = (frame(m)+1)*1024, in place.
// ---------------------------------------------------------------------------
__global__ __launch_bounds__(256) void softmax_kernel(float* __restrict__ Sc)
{
    int m = blockIdx.x;
    int L4 = ((m / NHW + 1) * NHW) >> 2;
    float4* row = (float4*)(Sc + (size_t)m * S);
    int tid = threadIdx.x;
    __shared__ float red[256];

    float mx = -3.4e38f;
    for (int i = tid; i < L4; i += 256) {
        float4 v = row[i];
        mx = fmaxf(mx, fmaxf(fmaxf(v.x, v.y), fmaxf(v.z, v.w)));
    }
    red[tid] = mx;
    __syncthreads();
    for (int s = 128; s > 0; s >>= 1) {
        if (tid < s) red[tid] = fmaxf(red[tid], red[tid + s]);
        __syncthreads();
    }
    mx = red[0];
    __syncthreads();

    float sum = 0.f;
    for (int i = tid; i < L4; i += 256) {
        float4 v = row[i];
        v.x = __expf(v.x - mx); v.y = __expf(v.y - mx);
        v.z = __expf(v.z - mx); v.w = __expf(v.w - mx);
        row[i] = v;
        sum += v.x + v.y + v.z + v.w;
    }
    red[tid] = sum;
    __syncthreads();
    for (int s = 128; s > 0; s >>= 1) {
        if (tid < s) red[tid] += red[tid + s];
        __syncthreads();
    }
    float inv = 1.f / red[0];
    for (int i = tid; i < L4; i += 256) {
        float4 v = row[i];
        v.x *= inv; v.y *= inv; v.z *= inv; v.w *= inv;
        row[i] = v;
    }
}

// ---------------------------------------------------------------------------
// P @ V : out[m, c] = sum_{k < L(m)} P[m, k] * V[k, c]
// ---------------------------------------------------------------------------
__global__ __launch_bounds__(256) void gemm_pv_kernel(
    const float* __restrict__ P, const float* __restrict__ V,
    float* __restrict__ out)
{
    __shared__ float As[BK][BM + 4];
    __shared__ float Bs[BK][BN + 4];
    int tid = threadIdx.x;
    int m0 = blockIdx.x * BM;
    int n0 = blockIdx.y * BN;
    int L = (m0 / NHW + 1) * NHW;
    int ty = tid >> 4, tx = tid & 15;
    int la_r = tid >> 2, la_c = (tid & 3) * 4;
    int lb_r = tid >> 4, lb_c = (tid & 15) * 4;

    const float* a_ptr = P + (size_t)(m0 + la_r) * S + la_c;
    const float* b_ptr = V + (size_t)lb_r * CC + n0 + lb_c;

    float acc[4][4] = {{0.f,0.f,0.f,0.f},{0.f,0.f,0.f,0.f},{0.f,0.f,0.f,0.f},{0.f,0.f,0.f,0.f}};

    for (int kc = 0; kc < L; kc += BK) {
        float4 av = *(const float4*)(a_ptr + kc);
        float4 bv = *(const float4*)(b_ptr + (size_t)kc * CC);
        As[la_c + 0][la_r] = av.x; As[la_c + 1][la_r] = av.y;
        As[la_c + 2][la_r] = av.z; As[la_c + 3][la_r] = av.w;
        *(float4*)&Bs[lb_r][lb_c] = bv;
        __syncthreads();
#pragma unroll
        for (int k = 0; k < BK; ++k) {
            float4 a = *(const float4*)&As[k][ty * 4];
            float4 b = *(const float4*)&Bs[k][tx * 4];
            acc[0][0] += a.x * b.x; acc[0][1] += a.x * b.y; acc[0][2] += a.x * b.z; acc[0][3] += a.x * b.w;
            acc[1][0] += a.y * b.x; acc[1][1] += a.y * b.y; acc[1][2] += a.y * b.z; acc[1][3] += a.y * b.w;
            acc[2][0] += a.z * b.x; acc[2][1] += a.z * b.y; acc[2][2] += a.z * b.z; acc[2][3] += a.z * b.w;
            acc[3][0] += a.w * b.x; acc[3][1] += a.w * b.y; acc[3][2] += a.w * b.z; acc[3][3] += a.w * b.w;
        }
        __syncthreads();
    }

#pragma unroll
    for (int i = 0; i < 4; ++i) {
        int mm = m0 + ty * 4 + i;
        float4 o = make_float4(acc[i][0], acc[i][1], acc[i][2], acc[i][3]);
        *(float4*)&out[(size_t)mm * CC + (n0 + tx * 4)] = o;
    }
}

// ---------------------------------------------------------------------------
extern "C" void kernel_launch(void* const* d_in, const int* in_sizes, int n_in,
                              void* d_out, int out_size)
{
    const float* x    = (const float*)d_in[0];
    const float* r1g1 = (const float*)d_in[1];
    const float* r1w1 = (const float*)d_in[2];
    const float* r1b1 = (const float*)d_in[3];
    const float* r1g2 = (const float*)d_in[4];
    const float* r1w2 = (const float*)d_in[5];
    const float* r1b2 = (const float*)d_in[6];
    const float* atg  = (const float*)d_in[7];
    const float* qw   = (const float*)d_in[8];
    const float* qb   = (const float*)d_in[9];
    const float* kw   = (const float*)d_in[10];
    const float* kb   = (const float*)d_in[11];
    const float* vw   = (const float*)d_in[12];
    const float* vb   = (const float*)d_in[13];
    const float* pw   = (const float*)d_in[14];
    const float* pb   = (const float*)d_in[15];
    const float* r2g1 = (const float*)d_in[16];
    const float* r2w1 = (const float*)d_in[17];
    const float* r2b1 = (const float*)d_in[18];
    const float* r2g2 = (const float*)d_in[19];
    const float* r2w2 = (const float*)d_in[20];
    const float* r2b2 = (const float*)d_in[21];
    float* out = (float*)d_out;

    float *a, *b, *c, *k, *v, *sc;
    cudaGetSymbolAddress((void**)&a,  g_a);
    cudaGetSymbolAddress((void**)&b,  g_b);
    cudaGetSymbolAddress((void**)&c,  g_c);
    cudaGetSymbolAddress((void**)&k,  g_k);
    cudaGetSymbolAddress((void**)&v,  g_v);
    cudaGetSymbolAddress((void**)&sc, g_scores);

    dim3 blk(256);
    dim3 convGrid(S / BM, CC / BN);   // 128 x 8
    dim3 qkGrid(S / BM, S / BN);      // 128 x 128 (upper blocks early-exit)
    dim3 pvGrid(S / BM, CC / BN);

    // ---- resnet 1 ----
    rmsnorm_kernel<<<S, blk>>>(x, r1g1, a, 1);
    gemm_conv_kernel<<<convGrid, blk>>>(a, r1w1, r1b1, nullptr, b, 27);
    rmsnorm_kernel<<<S, blk>>>(b, r1g2, a, 1);
    gemm_conv_kernel<<<convGrid, blk>>>(a, r1w2, r1b2, x, b, 27);       // b = resnet1 out

    // ---- attention ----
    rmsnorm_kernel<<<S, blk>>>(b, atg, a, 0);                           // a = xn
    gemm_conv_kernel<<<convGrid, blk>>>(a, qw, qb, nullptr, c, 1);      // c = Q
    gemm_conv_kernel<<<convGrid, blk>>>(a, kw, kb, nullptr, k, 1);      // k = K
    gemm_conv_kernel<<<convGrid, blk>>>(a, vw, vb, nullptr, v, 1);      // v = V
    gemm_qk_kernel<<<qkGrid, blk>>>(c, k, sc);
    softmax_kernel<<<S, blk>>>(sc);
    gemm_pv_kernel<<<pvGrid, blk>>>(sc, v, a);                          // a = attn out (pre-proj)
    gemm_conv_kernel<<<convGrid, blk>>>(a, pw, pb, b, c, 1);            // c = attn block out

    // ---- resnet 2 ----
    rmsnorm_kernel<<<S, blk>>>(c, r2g1, a, 1);
    gemm_conv_kernel<<<convGrid, blk>>>(a, r2w1, r2b1, nullptr, b, 27);
    rmsnorm_kernel<<<S, blk>>>(b, r2g2, a, 1);
    gemm_conv_kernel<<<convGrid, blk>>>(a, r2w2, r2b2, c, out, 27);
}

// round 2
// speedup vs baseline: 1.5407x; 1.5407x over previous
#include <cuda_runtime.h>
#include <mma.h>
#include <math.h>

using namespace nvcuda;

#define S   8192
#define CC  512
#define NHW 1024

// Scratch (allocation-free rule: __device__ globals)
__device__ float g_a[S * CC];
__device__ float g_b[S * CC];
__device__ float g_c[S * CC];
__device__ float g_k[S * CC];
__device__ float g_v[S * CC];
__device__ float g_scores[(size_t)S * S];

__device__ __forceinline__ void cp_async16(void* smem, const void* gmem) {
    unsigned s = (unsigned)__cvta_generic_to_shared(smem);
    asm volatile("cp.async.cg.shared.global [%0], [%1], 16;\n" :: "r"(s), "l"(gmem));
}
__device__ __forceinline__ void cp_commit() { asm volatile("cp.async.commit_group;\n"); }
__device__ __forceinline__ void cp_wait1()  { asm volatile("cp.async.wait_group 1;\n"); }
__device__ __forceinline__ void cp_wait0()  { asm volatile("cp.async.wait_group 0;\n"); }

// ---------------------------------------------------------------------------
// rmsnorm (+ optional silu)
// ---------------------------------------------------------------------------
__global__ __launch_bounds__(256) void rmsnorm_kernel(
    const float* __restrict__ X, const float* __restrict__ g,
    float* __restrict__ out, int dosilu)
{
    int m = blockIdx.x;
    const float* xr = X + (size_t)m * CC;
    float* orow = out + (size_t)m * CC;
    int tid = threadIdx.x;
    float x0 = xr[tid], x1 = xr[tid + 256];
    __shared__ float red[256];
    red[tid] = x0 * x0 + x1 * x1;
    __syncthreads();
    for (int s = 128; s > 0; s >>= 1) {
        if (tid < s) red[tid] += red[tid + s];
        __syncthreads();
    }
    float scale = 22.627416997969522f / (sqrtf(red[0]) + 1e-8f);
    float y0 = x0 * scale * g[tid];
    float y1 = x1 * scale * g[tid + 256];
    if (dosilu) {
        y0 = y0 / (1.0f + __expf(-y0));
        y1 = y1 / (1.0f + __expf(-y1));
    }
    orow[tid] = y0;
    orow[tid + 256] = y1;
}

// ===========================================================================
// tf32 WMMA GEMM, conv-as-GEMM variant.
// out[m,n] = sum_tap sum_k A[src(m,tap),k] * W[tap,k,n] + bias[n] (+ res[m,n])
// Block 128x128, BK=16, 8 warps (2x4), warp tile 64x32.
// ===========================================================================
#define LDA_S 20   // As row stride (16 + 4 pad)
#define LDB_S 132  // Bs row stride (128 + 4 pad)

__global__ __launch_bounds__(256, 1) void wgemm_conv(
    const float* __restrict__ A, const float* __restrict__ W,
    const float* __restrict__ bias, const float* __restrict__ res,
    float* __restrict__ out, int ntaps)
{
    __shared__ float As[2][128 * LDA_S];
    __shared__ float Bs[2][16 * LDB_S];
    __shared__ float stage[8][256];

    int tid = threadIdx.x, wid = tid >> 5, lane = tid & 31;
    int m0 = blockIdx.x * 128, n0 = blockIdx.y * 128;
    int warpM = wid & 1, warpN = wid >> 1;

    // loader indices
    int rA[2], cA[2], tA[2], yA[2], xA[2];
    int rB[2], cB[2];
#pragma unroll
    for (int i = 0; i < 2; ++i) {
        int f = tid + i * 256;
        rA[i] = f >> 2;  cA[i] = (f & 3) * 4;
        int m = m0 + rA[i];
        tA[i] = m >> 10; yA[i] = (m >> 5) & 31; xA[i] = m & 31;
        rB[i] = f >> 5;  cB[i] = (f & 31) * 4;
    }

    wmma::fragment<wmma::matrix_a, 16, 16, 8, wmma::precision::tf32, wmma::row_major> af[4];
    wmma::fragment<wmma::matrix_b, 16, 16, 8, wmma::precision::tf32, wmma::row_major> bf[2];
    wmma::fragment<wmma::accumulator, 16, 16, 8, float> acc[4][2];
#pragma unroll
    for (int i = 0; i < 4; ++i)
#pragma unroll
        for (int j = 0; j < 2; ++j) wmma::fill_fragment(acc[i][j], 0.0f);

    int nIter = ntaps * 32;

    auto preload = [&](int it, int buf) {
        int tap = it >> 5;
        int kc = (it & 31) << 4;
#pragma unroll
        for (int i = 0; i < 2; ++i) {
            int src;
            if (ntaps == 1) {
                src = m0 + rA[i];
            } else {
                int dt = tap / 9, dy = (tap / 3) % 3, dx = tap % 3;
                int st = tA[i] + dt - 2; st = st < 0 ? 0 : st;
                int sy = yA[i] + dy - 1; sy = sy < 0 ? 0 : (sy > 31 ? 31 : sy);
                int sx = xA[i] + dx - 1; sx = sx < 0 ? 0 : (sx > 31 ? 31 : sx);
                src = (st << 10) + (sy << 5) + sx;
            }
            cp_async16(&As[buf][rA[i] * LDA_S + cA[i]],
                       A + (size_t)src * CC + kc + cA[i]);
        }
#pragma unroll
        for (int i = 0; i < 2; ++i) {
            cp_async16(&Bs[buf][rB[i] * LDB_S + cB[i]],
                       W + ((size_t)tap * CC + kc + rB[i]) * CC + n0 + cB[i]);
        }
        cp_commit();
    };

    preload(0, 0);
    for (int it = 0; it < nIter; ++it) {
        int buf = it & 1;
        if (it + 1 < nIter) { preload(it + 1, buf ^ 1); cp_wait1(); }
        else cp_wait0();
        __syncthreads();
#pragma unroll
        for (int kk = 0; kk < 16; kk += 8) {
#pragma unroll
            for (int i = 0; i < 4; ++i)
                wmma::load_matrix_sync(af[i], &As[buf][(warpM * 64 + i * 16) * LDA_S + kk], LDA_S);
#pragma unroll
            for (int j = 0; j < 2; ++j)
                wmma::load_matrix_sync(bf[j], &Bs[buf][kk * LDB_S + warpN * 32 + j * 16], LDB_S);
#pragma unroll
            for (int i = 0; i < 4; ++i)
#pragma unroll
                for (int j = 0; j < 2; ++j)
                    wmma::mma_sync(acc[i][j], af[i], bf[j], acc[i][j]);
        }
        __syncthreads();
    }

    // epilogue: bias (+res) via per-warp staging
#pragma unroll
    for (int i = 0; i < 4; ++i) {
#pragma unroll
        for (int j = 0; j < 2; ++j) {
            wmma::store_matrix_sync(&stage[wid][0], acc[i][j], 16, wmma::mem_row_major);
            __syncwarp();
#pragma unroll
            for (int e = 0; e < 8; ++e) {
                int idx = lane * 8 + e;
                int r = idx >> 4, c = idx & 15;
                int gm = m0 + warpM * 64 + i * 16 + r;
                int gn = n0 + warpN * 32 + j * 16 + c;
                float v = stage[wid][idx] + bias[gn];
                if (res) v += res[(size_t)gm * CC + gn];
                out[(size_t)gm * CC + gn] = v;
            }
            __syncwarp();
        }
    }
}

// ===========================================================================
// QK^T (tf32): Sc[q,k] = scale * dot(Q[q,:], K[k,:]) for frame(k) <= frame(q)
// ===========================================================================
__global__ __launch_bounds__(256, 1) void wgemm_qk(
    const float* __restrict__ Q, const float* __restrict__ Km,
    float* __restrict__ Sc)
{
    int q0 = blockIdx.x * 128, k0 = blockIdx.y * 128;
    if ((k0 / NHW) > (q0 / NHW)) return;

    __shared__ float As[2][128 * LDA_S];
    __shared__ float Ks[2][128 * LDA_S];

    int tid = threadIdx.x, wid = tid >> 5;
    int warpM = wid & 1, warpN = wid >> 1;

    int rA[2], cA[2];
#pragma unroll
    for (int i = 0; i < 2; ++i) {
        int f = tid + i * 256;
        rA[i] = f >> 2; cA[i] = (f & 3) * 4;
    }

    wmma::fragment<wmma::matrix_a, 16, 16, 8, wmma::precision::tf32, wmma::row_major> af[4];
    wmma::fragment<wmma::matrix_b, 16, 16, 8, wmma::precision::tf32, wmma::col_major> bf[2];
    wmma::fragment<wmma::accumulator, 16, 16, 8, float> acc[4][2];
#pragma unroll
    for (int i = 0; i < 4; ++i)
#pragma unroll
        for (int j = 0; j < 2; ++j) wmma::fill_fragment(acc[i][j], 0.0f);

    auto preload = [&](int it, int buf) {
        int kc = it << 4;
#pragma unroll
        for (int i = 0; i < 2; ++i) {
            cp_async16(&As[buf][rA[i] * LDA_S + cA[i]],
                       Q + (size_t)(q0 + rA[i]) * CC + kc + cA[i]);
            cp_async16(&Ks[buf][rA[i] * LDA_S + cA[i]],
                       Km + (size_t)(k0 + rA[i]) * CC + kc + cA[i]);
        }
        cp_commit();
    };

    int nIter = CC / 16;
    preload(0, 0);
    for (int it = 0; it < nIter; ++it) {
        int buf = it & 1;
        if (it + 1 < nIter) { preload(it + 1, buf ^ 1); cp_wait1(); }
        else cp_wait0();
        __syncthreads();
#pragma unroll
        for (int kk = 0; kk < 16; kk += 8) {
#pragma unroll
            for (int i = 0; i < 4; ++i)
                wmma::load_matrix_sync(af[i], &As[buf][(warpM * 64 + i * 16) * LDA_S + kk], LDA_S);
#pragma unroll
            for (int j = 0; j < 2; ++j)
                wmma::load_matrix_sync(bf[j], &Ks[buf][(warpN * 32 + j * 16) * LDA_S + kk], LDA_S);
#pragma unroll
            for (int i = 0; i < 4; ++i)
#pragma unroll
                for (int j = 0; j < 2; ++j)
                    wmma::mma_sync(acc[i][j], af[i], bf[j], acc[i][j]);
        }
        __syncthreads();
    }

    const float scale = 0.044194173824159216f;  // 1/sqrt(512)
#pragma unroll
    for (int i = 0; i < 4; ++i)
#pragma unroll
        for (int j = 0; j < 2; ++j) {
#pragma unroll
            for (int e = 0; e < acc[i][j].num_elements; ++e) acc[i][j].x[e] *= scale;
            wmma::store_matrix_sync(
                &Sc[(size_t)(q0 + warpM * 64 + i * 16) * S + k0 + warpN * 32 + j * 16],
                acc[i][j], S, wmma::mem_row_major);
        }
}

// ===========================================================================
// P @ V (tf32): out[m,c] = sum_{k<L(m)} P[m,k] * V[k,c]
// ===========================================================================
__global__ __launch_bounds__(256, 1) void wgemm_pv(
    const float* __restrict__ P, const float* __restrict__ V,
    float* __restrict__ out)
{
    __shared__ float As[2][128 * LDA_S];
    __shared__ float Bs[2][16 * LDB_S];

    int tid = threadIdx.x, wid = tid >> 5;
    int m0 = blockIdx.x * 128, n0 = blockIdx.y * 128;
    int warpM = wid & 1, warpN = wid >> 1;
    int L = (m0 / NHW + 1) * NHW;

    int rA[2], cA[2], rB[2], cB[2];
#pragma unroll
    for (int i = 0; i < 2; ++i) {
        int f = tid + i * 256;
        rA[i] = f >> 2;  cA[i] = (f & 3) * 4;
        rB[i] = f >> 5;  cB[i] = (f & 31) * 4;
    }

    wmma::fragment<wmma::matrix_a, 16, 16, 8, wmma::precision::tf32, wmma::row_major> af[4];
    wmma::fragment<wmma::matrix_b, 16, 16, 8, wmma::precision::tf32, wmma::row_major> bf[2];
    wmma::fragment<wmma::accumulator, 16, 16, 8, float> acc[4][2];
#pragma unroll
    for (int i = 0; i < 4; ++i)
#pragma unroll
        for (int j = 0; j < 2; ++j) wmma::fill_fragment(acc[i][j], 0.0f);

    auto preload = [&](int it, int buf) {
        int kc = it << 4;
#pragma unroll
        for (int i = 0; i < 2; ++i) {
            cp_async16(&As[buf][rA[i] * LDA_S + cA[i]],
                       P + (size_t)(m0 + rA[i]) * S + kc + cA[i]);
            cp_async16(&Bs[buf][rB[i] * LDB_S + cB[i]],
                       V + (size_t)(kc + rB[i]) * CC + n0 + cB[i]);
        }
        cp_commit();
    };

    int nIter = L >> 4;
    preload(0, 0);
    for (int it = 0; it < nIter; ++it) {
        int buf = it & 1;
        if (it + 1 < nIter) { preload(it + 1, buf ^ 1); cp_wait1(); }
        else cp_wait0();
        __syncthreads();
#pragma unroll
        for (int kk = 0; kk < 16; kk += 8) {
#pragma unroll
            for (int i = 0; i < 4; ++i)
                wmma::load_matrix_sync(af[i], &As[buf][(warpM * 64 + i * 16) * LDA_S + kk], LDA_S);
#pragma unroll
            for (int j = 0; j < 2; ++j)
                wmma::load_matrix_sync(bf[j], &Bs[buf][kk * LDB_S + warpN * 32 + j * 16], LDB_S);
#pragma unroll
            for (int i = 0; i < 4; ++i)
#pragma unroll
                for (int j = 0; j < 2; ++j)
                    wmma::mma_sync(acc[i][j], af[i], bf[j], acc[i][j]);
        }
        __syncthreads();
    }

#pragma unroll
    for (int i = 0; i < 4; ++i)
#pragma unroll
        for (int j = 0; j < 2; ++j)
            wmma::store_matrix_sync(
                &out[(size_t)(m0 + warpM * 64 + i * 16) * CC + n0 + warpN * 32 + j * 16],
                acc[i][j], CC, wmma::mem_row_major);
}

// ---------------------------------------------------------------------------
// Row softmax over valid length L = (frame(m)+1)*1024, in place.
// ---------------------------------------------------------------------------
__global__ __launch_bounds__(256) void softmax_kernel(float* __restrict__ Sc)
{
    int m = blockIdx.x;
    int L4 = ((m / NHW + 1) * NHW) >> 2;
    float4* row = (float4*)(Sc + (size_t)m * S);
    int tid = threadIdx.x;
    __shared__ float red[256];

    float mx = -3.4e38f;
    for (int i = tid; i < L4; i += 256) {
        float4 v = row[i];
        mx = fmaxf(mx, fmaxf(fmaxf(v.x, v.y), fmaxf(v.z, v.w)));
    }
    red[tid] = mx;
    __syncthreads();
    for (int s = 128; s > 0; s >>= 1) {
        if (tid < s) red[tid] = fmaxf(red[tid], red[tid + s]);
        __syncthreads();
    }
    mx = red[0];
    __syncthreads();

    float sum = 0.f;
    for (int i = tid; i < L4; i += 256) {
        float4 v = row[i];
        v.x = __expf(v.x - mx); v.y = __expf(v.y - mx);
        v.z = __expf(v.z - mx); v.w = __expf(v.w - mx);
        row[i] = v;
        sum += v.x + v.y + v.z + v.w;
    }
    red[tid] = sum;
    __syncthreads();
    for (int s = 128; s > 0; s >>= 1) {
        if (tid < s) red[tid] += red[tid + s];
        __syncthreads();
    }
    float inv = 1.f / red[0];
    for (int i = tid; i < L4; i += 256) {
        float4 v = row[i];
        v.x *= inv; v.y *= inv; v.z *= inv; v.w *= inv;
        row[i] = v;
    }
}

// ---------------------------------------------------------------------------
extern "C" void kernel_launch(void* const* d_in, const int* in_sizes, int n_in,
                              void* d_out, int out_size)
{
    const float* x    = (const float*)d_in[0];
    const float* r1g1 = (const float*)d_in[1];
    const float* r1w1 = (const float*)d_in[2];
    const float* r1b1 = (const float*)d_in[3];
    const float* r1g2 = (const float*)d_in[4];
    const float* r1w2 = (const float*)d_in[5];
    const float* r1b2 = (const float*)d_in[6];
    const float* atg  = (const float*)d_in[7];
    const float* qw   = (const float*)d_in[8];
    const float* qb   = (const float*)d_in[9];
    const float* kw   = (const float*)d_in[10];
    const float* kb   = (const float*)d_in[11];
    const float* vw   = (const float*)d_in[12];
    const float* vb   = (const float*)d_in[13];
    const float* pw   = (const float*)d_in[14];
    const float* pb   = (const float*)d_in[15];
    const float* r2g1 = (const float*)d_in[16];
    const float* r2w1 = (const float*)d_in[17];
    const float* r2b1 = (const float*)d_in[18];
    const float* r2g2 = (const float*)d_in[19];
    const float* r2w2 = (const float*)d_in[20];
    const float* r2b2 = (const float*)d_in[21];
    float* out = (float*)d_out;

    float *a, *b, *c, *k, *v, *sc;
    cudaGetSymbolAddress((void**)&a,  g_a);
    cudaGetSymbolAddress((void**)&b,  g_b);
    cudaGetSymbolAddress((void**)&c,  g_c);
    cudaGetSymbolAddress((void**)&k,  g_k);
    cudaGetSymbolAddress((void**)&v,  g_v);
    cudaGetSymbolAddress((void**)&sc, g_scores);

    dim3 blk(256);
    dim3 gGrid(S / 128, CC / 128);    // 64 x 4
    dim3 qkGrid(S / 128, S / 128);    // 64 x 64 (invalid blocks early-exit)

    // ---- resnet 1 ----
    rmsnorm_kernel<<<S, blk>>>(x, r1g1, a, 1);
    wgemm_conv<<<gGrid, blk>>>(a, r1w1, r1b1, nullptr, b, 27);
    rmsnorm_kernel<<<S, blk>>>(b, r1g2, a, 1);
    wgemm_conv<<<gGrid, blk>>>(a, r1w2, r1b2, x, b, 27);      // b = resnet1 out

    // ---- attention ----
    rmsnorm_kernel<<<S, blk>>>(b, atg, a, 0);                 // a = xn
    wgemm_conv<<<gGrid, blk>>>(a, qw, qb, nullptr, c, 1);     // c = Q
    wgemm_conv<<<gGrid, blk>>>(a, kw, kb, nullptr, k, 1);     // k = K
    wgemm_conv<<<gGrid, blk>>>(a, vw, vb, nullptr, v, 1);     // v = V
    wgemm_qk<<<qkGrid, blk>>>(c, k, sc);
    softmax_kernel<<<S, blk>>>(sc);
    wgemm_pv<<<gGrid, blk>>>(sc, v, a);                       // a = attn (pre-proj)
    wgemm_conv<<<gGrid, blk>>>(a, pw, pb, b, c, 1);           // c = attn out

    // ---- resnet 2 ----
    rmsnorm_kernel<<<S, blk>>>(c, r2g1, a, 1);
    wgemm_conv<<<gGrid, blk>>>(a, r2w1, r2b1, nullptr, b, 27);
    rmsnorm_kernel<<<S, blk>>>(b, r2g2, a, 1);
    wgemm_conv<<<gGrid, blk>>>(a, r2w2, r2b2, c, out, 27);
}

// round 4
// speedup vs baseline: 7.0012x; 4.5443x over previous
#include <cuda_runtime.h>
#include <cuda_fp16.h>
#include <math.h>
#include <stdint.h>

#define S    8192
#define CC   512
#define NHW  1024
#define BM   128
#define BN   128
#define BK   64
#define NST  3
#define STAGE_BYTES 16384              // 128 rows x 128 bytes (64 halves)
#define SMT (6 * STAGE_BYTES)          // 3 stages x (A + B) = 96KB

// ---------------- scratch (__device__ globals) ----------------
__device__ float  g_f1[S * CC];
__device__ float  g_f2[S * CC];
__device__ float  g_sc[(size_t)S * S];       // fp32 scores
__device__ __half g_ha[S * CC];              // normed activations
__device__ __half g_ha2[S * CC];             // attn pre-proj
__device__ __half g_hq[S * CC];
__device__ __half g_hk[S * CC];
__device__ __half g_hv[S * CC];
__device__ __half g_hvt[CC * S];             // V^T
__device__ __half g_hp[(size_t)S * S];       // fp16 probabilities
__device__ __half g_hwt[CC * 27 * CC];       // transposed conv weight
__device__ __half g_hw1[CC * CC];            // transposed 1x1 weight

// ---------------- helpers ----------------
__device__ __forceinline__ uint32_t smem_u32(const void* p) {
    return (uint32_t)__cvta_generic_to_shared(p);
}
__device__ __forceinline__ void cp_async16(uint32_t smem, const void* gmem) {
    asm volatile("cp.async.cg.shared.global [%0], [%1], 16;\n" :: "r"(smem), "l"(gmem));
}
__device__ __forceinline__ void cp_commit() { asm volatile("cp.async.commit_group;\n"); }
__device__ __forceinline__ void cp_wait_n(int tail) {
    if (tail >= 2)      asm volatile("cp.async.wait_group 2;\n");
    else if (tail == 1) asm volatile("cp.async.wait_group 1;\n");
    else                asm volatile("cp.async.wait_group 0;\n");
}
#define SWZ(o) ((o) ^ (((o) >> 3) & 0x70))

__device__ __forceinline__ void ldm4(uint32_t* r, uint32_t addr) {
    asm volatile("ldmatrix.sync.aligned.m8n8.x4.shared.b16 {%0,%1,%2,%3}, [%4];\n"
                 : "=r"(r[0]), "=r"(r[1]), "=r"(r[2]), "=r"(r[3]) : "r"(addr));
}
__device__ __forceinline__ void mma16816(float* c, const uint32_t* a, uint32_t b0, uint32_t b1) {
    asm volatile(
        "mma.sync.aligned.m16n8k16.row.col.f32.f16.f16.f32 "
        "{%0,%1,%2,%3}, {%4,%5,%6,%7}, {%8,%9}, {%0,%1,%2,%3};\n"
        : "+f"(c[0]), "+f"(c[1]), "+f"(c[2]), "+f"(c[3])
        : "r"(a[0]), "r"(a[1]), "r"(a[2]), "r"(a[3]), "r"(b0), "r"(b1));
}

// ===========================================================================
// Unified fp16 mma.sync GEMM.
// out[m,n] = scale * (sum_k A[src(m),k] * Bt[n,k]) (+bias) (+res)
// mode: 0 = linear, 1 = conv27, 2 = QK (block skip + fp32 out), 3 = PV (L-limited)
// ===========================================================================
__global__ __launch_bounds__(256, 2) void tc_gemm(
    const __half* __restrict__ A, int lda,
    const __half* __restrict__ Bt, int ldb,
    const float* __restrict__ bias, const float* __restrict__ res,
    void* __restrict__ outp, int ldo, int out_half,
    int nIterIn, int mode, float scale)
{
    extern __shared__ char smem[];
    int tid = threadIdx.x;
    int m0 = blockIdx.x * BM;
    int n0 = blockIdx.y * BN;

    if (mode == 2 && (n0 >> 10) > (m0 >> 10)) return;

    int nIter = nIterIn;
    if (mode == 3) nIter = ((m0 >> 10) + 1) * (NHW / BK);

    uint32_t sbase = smem_u32(smem);

    // loader: tile = 128 rows x 128 bytes = 1024 16B chunks; 4 chunks/thread
    int arow[4], acol[4]; uint32_t csw[4];
    int at[4], ay[4], ax[4];
#pragma unroll
    for (int j = 0; j < 4; ++j) {
        int ch = tid + j * 256;
        arow[j] = ch >> 3; acol[j] = ch & 7;
        csw[j] = SWZ(arow[j] * 128 + acol[j] * 16);
        int m = m0 + arow[j];
        at[j] = m >> 10; ay[j] = (m >> 5) & 31; ax[j] = m & 31;
    }

    auto load_stage = [&](int it, int buf) {
        uint32_t sA = sbase + buf * STAGE_BYTES;
        uint32_t sB = sbase + 3 * STAGE_BYTES + buf * STAGE_BYTES;
        int kcA, dt = 0, dy = 0, dx = 0;
        if (mode == 1) {
            int tap = it >> 3; kcA = (it & 7) << 6;
            dt = tap / 9 - 2; dy = (tap / 3) % 3 - 1; dx = tap % 3 - 1;
        } else kcA = it << 6;
        int kcB = it << 6;
#pragma unroll
        for (int j = 0; j < 4; ++j) {
            int src;
            if (mode == 1) {
                int st = at[j] + dt; st = st < 0 ? 0 : st;
                int sy = ay[j] + dy; sy = sy < 0 ? 0 : (sy > 31 ? 31 : sy);
                int sx = ax[j] + dx; sx = sx < 0 ? 0 : (sx > 31 ? 31 : sx);
                src = (st << 10) + (sy << 5) + sx;
            } else src = m0 + arow[j];
            cp_async16(sA + csw[j], A + (size_t)src * lda + kcA + acol[j] * 8);
            cp_async16(sB + csw[j], Bt + (size_t)(n0 + arow[j]) * ldb + kcB + acol[j] * 8);
        }
        cp_commit();
    };

    int wid = tid >> 5, lane = tid & 31;
    int warpM = wid & 1, warpN = wid >> 1;        // 2 x 4 warps, warp tile 64x32
    int rA = (lane & 7) + ((lane >> 3) & 1) * 8;  // ldmatrix row-in-16
    int khalf = (lane >> 4) & 1;                  // +16B for k-hi

    float acc[4][4][4];
#pragma unroll
    for (int i = 0; i < 4; ++i)
#pragma unroll
        for (int j = 0; j < 4; ++j)
#pragma unroll
            for (int e = 0; e < 4; ++e) acc[i][j][e] = 0.f;

    for (int s = 0; s < NST && s < nIter; ++s) load_stage(s, s);

    for (int it = 0; it < nIter; ++it) {
        int buf = it % NST;
        cp_wait_n(nIter - 1 - it);
        __syncthreads();
        uint32_t sA = sbase + buf * STAGE_BYTES;
        uint32_t sB = sbase + 3 * STAGE_BYTES + buf * STAGE_BYTES;
#pragma unroll
        for (int kk = 0; kk < 4; ++kk) {
            uint32_t afr[4][4], bfr[2][4];
#pragma unroll
            for (int mi = 0; mi < 4; ++mi)
                ldm4(afr[mi], sA + SWZ((warpM * 64 + mi * 16 + rA) * 128 + kk * 32 + khalf * 16));
#pragma unroll
            for (int nj = 0; nj < 2; ++nj)
                ldm4(bfr[nj], sB + SWZ((warpN * 32 + nj * 16 + rA) * 128 + kk * 32 + khalf * 16));
#pragma unroll
            for (int mi = 0; mi < 4; ++mi)
#pragma unroll
                for (int nf = 0; nf < 4; ++nf) {
                    int nj = nf >> 1, h = nf & 1;
                    mma16816(acc[mi][nf], afr[mi], bfr[nj][h], bfr[nj][h + 2]);
                }
        }
        __syncthreads();
        if (it + NST < nIter) load_stage(it + NST, buf);
    }

    // epilogue
    int r0 = lane >> 2, c0 = (lane & 3) * 2;
#pragma unroll
    for (int mi = 0; mi < 4; ++mi)
#pragma unroll
        for (int nf = 0; nf < 4; ++nf) {
            int gm = m0 + warpM * 64 + mi * 16 + r0;
            int gn = n0 + warpN * 32 + nf * 8 + c0;
#pragma unroll
            for (int hrow = 0; hrow < 2; ++hrow) {
                int m = gm + hrow * 8;
                float vx = acc[mi][nf][hrow * 2 + 0] * scale;
                float vy = acc[mi][nf][hrow * 2 + 1] * scale;
                if (bias) { vx += bias[gn]; vy += bias[gn + 1]; }
                if (res) {
                    const float2 rr = *(const float2*)&res[(size_t)m * ldo + gn];
                    vx += rr.x; vy += rr.y;
                }
                if (out_half) {
                    __half2* o = (__half2*)((__half*)outp + (size_t)m * ldo + gn);
                    *o = __floats2half2_rn(vx, vy);
                } else {
                    float2* o = (float2*)((float*)outp + (size_t)m * ldo + gn);
                    *o = make_float2(vx, vy);
                }
            }
        }
}

// ---------------------------------------------------------------------------
// weight convert+transpose: src fp32 [R][Cn] -> dst fp16 [Cn][R]
// ---------------------------------------------------------------------------
__global__ __launch_bounds__(256) void wcvt(
    const float* __restrict__ src, __half* __restrict__ dst, int R, int Cn)
{
    __shared__ float t[32][33];
    int r0 = blockIdx.x * 32, c0 = blockIdx.y * 32;
    int x = threadIdx.x & 31, y = threadIdx.x >> 5;
#pragma unroll
    for (int i = 0; i < 4; ++i)
        t[y + i * 8][x] = src[(size_t)(r0 + y + i * 8) * Cn + c0 + x];
    __syncthreads();
#pragma unroll
    for (int i = 0; i < 4; ++i)
        dst[(size_t)(c0 + y + i * 8) * R + r0 + x] = __float2half_rn(t[x][y + i * 8]);
}

// half transpose: src [R][Cn] -> dst [Cn][R]
__global__ __launch_bounds__(256) void htrans(
    const __half* __restrict__ src, __half* __restrict__ dst, int R, int Cn)
{
    __shared__ __half t[32][34];
    int r0 = blockIdx.x * 32, c0 = blockIdx.y * 32;
    int x = threadIdx.x & 31, y = threadIdx.x >> 5;
#pragma unroll
    for (int i = 0; i < 4; ++i)
        t[y + i * 8][x] = src[(size_t)(r0 + y + i * 8) * Cn + c0 + x];
    __syncthreads();
#pragma unroll
    for (int i = 0; i < 4; ++i)
        dst[(size_t)(c0 + y + i * 8) * R + r0 + x] = t[x][y + i * 8];
}

// ---------------------------------------------------------------------------
// rmsnorm (+ optional silu): fp32 in, fp16 out
// ---------------------------------------------------------------------------
__global__ __launch_bounds__(256) void rmsnorm_kernel(
    const float* __restrict__ X, const float* __restrict__ g,
    __half* __restrict__ out, int dosilu)
{
    int m = blockIdx.x;
    const float* xr = X + (size_t)m * CC;
    __half* orow = out + (size_t)m * CC;
    int tid = threadIdx.x;
    float x0 = xr[tid], x1 = xr[tid + 256];
    __shared__ float red[256];
    red[tid] = x0 * x0 + x1 * x1;
    __syncthreads();
    for (int s = 128; s > 0; s >>= 1) {
        if (tid < s) red[tid] += red[tid + s];
        __syncthreads();
    }
    float scale = 22.627416997969522f / (sqrtf(red[0]) + 1e-8f);
    float y0 = x0 * scale * g[tid];
    float y1 = x1 * scale * g[tid + 256];
    if (dosilu) {
        y0 = y0 / (1.0f + __expf(-y0));
        y1 = y1 / (1.0f + __expf(-y1));
    }
    orow[tid] = __float2half_rn(y0);
    orow[tid + 256] = __float2half_rn(y1);
}

// ---------------------------------------------------------------------------
// softmax: fp32 scores -> fp16 probabilities, valid length L = (frame+1)*1024
// single-read online (max,sum), second pass writes normalized fp16.
// ---------------------------------------------------------------------------
__global__ __launch_bounds__(256) void softmax_kernel(
    const float* __restrict__ Sc, __half* __restrict__ P)
{
    int m = blockIdx.x;
    int L4 = ((m >> 10) + 1) << 8;   // L/4
    const float4* row = (const float4*)(Sc + (size_t)m * S);
    __half2* prow = (__half2*)(P + (size_t)m * S);
    int tid = threadIdx.x;
    __shared__ float rm[256], rs[256];

    float mx = -3.4e38f, sm = 0.f;
    for (int i = tid; i < L4; i += 256) {
        float4 v = row[i];
        float bm = fmaxf(fmaxf(v.x, v.y), fmaxf(v.z, v.w));
        if (bm > mx) { sm *= __expf(mx - bm); mx = bm; }
        sm += __expf(v.x - mx) + __expf(v.y - mx) + __expf(v.z - mx) + __expf(v.w - mx);
    }
    rm[tid] = mx; rs[tid] = sm;
    __syncthreads();
    for (int s = 128; s > 0; s >>= 1) {
        if (tid < s) {
            float m2 = rm[tid + s], s2 = rs[tid + s];
            float M = fmaxf(rm[tid], m2);
            rs[tid] = rs[tid] * __expf(rm[tid] - M) + s2 * __expf(m2 - M);
            rm[tid] = M;
        }
        __syncthreads();
    }
    float M = rm[0];
    float inv = 1.f / rs[0];

    for (int i = tid; i < L4; i += 256) {
        float4 v = row[i];
        float p0 = __expf(v.x - M) * inv, p1 = __expf(v.y - M) * inv;
        float p2 = __expf(v.z - M) * inv, p3 = __expf(v.w - M) * inv;
        prow[i * 2 + 0] = __floats2half2_rn(p0, p1);
        prow[i * 2 + 1] = __floats2half2_rn(p2, p3);
    }
}

// ---------------------------------------------------------------------------
extern "C" void kernel_launch(void* const* d_in, const int* in_sizes, int n_in,
                              void* d_out, int out_size)
{
    const float* x    = (const float*)d_in[0];
    const float* r1g1 = (const float*)d_in[1];
    const float* r1w1 = (const float*)d_in[2];
    const float* r1b1 = (const float*)d_in[3];
    const float* r1g2 = (const float*)d_in[4];
    const float* r1w2 = (const float*)d_in[5];
    const float* r1b2 = (const float*)d_in[6];
    const float* atg  = (const float*)d_in[7];
    const float* qw   = (const float*)d_in[8];
    const float* qb   = (const float*)d_in[9];
    const float* kw   = (const float*)d_in[10];
    const float* kb   = (const float*)d_in[11];
    const float* vw   = (const float*)d_in[12];
    const float* vb   = (const float*)d_in[13];
    const float* pw   = (const float*)d_in[14];
    const float* pb   = (const float*)d_in[15];
    const float* r2g1 = (const float*)d_in[16];
    const float* r2w1 = (const float*)d_in[17];
    const float* r2b1 = (const float*)d_in[18];
    const float* r2g2 = (const float*)d_in[19];
    const float* r2w2 = (const float*)d_in[20];
    const float* r2b2 = (const float*)d_in[21];
    float* out = (float*)d_out;

    float *f1, *f2, *sc;
    __half *ha, *ha2, *hq, *hk, *hv, *hvt, *hp, *hwt, *hw1;
    cudaGetSymbolAddress((void**)&f1,  g_f1);
    cudaGetSymbolAddress((void**)&f2,  g_f2);
    cudaGetSymbolAddress((void**)&sc,  g_sc);
    cudaGetSymbolAddress((void**)&ha,  g_ha);
    cudaGetSymbolAddress((void**)&ha2, g_ha2);
    cudaGetSymbolAddress((void**)&hq,  g_hq);
    cudaGetSymbolAddress((void**)&hk,  g_hk);
    cudaGetSymbolAddress((void**)&hv,  g_hv);
    cudaGetSymbolAddress((void**)&hvt, g_hvt);
    cudaGetSymbolAddress((void**)&hp,  g_hp);
    cudaGetSymbolAddress((void**)&hwt, g_hwt);
    cudaGetSymbolAddress((void**)&hw1, g_hw1);

    cudaFuncSetAttribute(tc_gemm, cudaFuncAttributeMaxDynamicSharedMemorySize, SMT);

    dim3 blk(256);
    dim3 gGrid(S / BM, CC / BN);      // 64 x 4
    dim3 qkGrid(S / BM, S / BN);      // 64 x 64
    dim3 wcGrid(27 * CC / 32, CC / 32);
    dim3 w1Grid(CC / 32, CC / 32);
    dim3 vtGrid(S / 32, CC / 32);
    const float qscale = 0.044194173824159216f;  // 1/sqrt(512)
    const int KC = 27 * CC;

    // ---- resnet 1 ----
    rmsnorm_kernel<<<S, blk>>>(x, r1g1, ha, 1);
    wcvt<<<wcGrid, blk>>>(r1w1, hwt, KC, CC);
    tc_gemm<<<gGrid, blk, SMT>>>(ha, CC, hwt, KC, r1b1, nullptr, f1, CC, 0, 27 * 8, 1, 1.f);
    rmsnorm_kernel<<<S, blk>>>(f1, r1g2, ha, 1);
    wcvt<<<wcGrid, blk>>>(r1w2, hwt, KC, CC);
    tc_gemm<<<gGrid, blk, SMT>>>(ha, CC, hwt, KC, r1b2, x, f1, CC, 0, 27 * 8, 1, 1.f);  // f1 = resnet1

    // ---- attention ----
    rmsnorm_kernel<<<S, blk>>>(f1, atg, ha, 0);
    wcvt<<<w1Grid, blk>>>(qw, hw1, CC, CC);
    tc_gemm<<<gGrid, blk, SMT>>>(ha, CC, hw1, CC, qb, nullptr, hq, CC, 1, 8, 0, 1.f);
    wcvt<<<w1Grid, blk>>>(kw, hw1, CC, CC);
    tc_gemm<<<gGrid, blk, SMT>>>(ha, CC, hw1, CC, kb, nullptr, hk, CC, 1, 8, 0, 1.f);
    wcvt<<<w1Grid, blk>>>(vw, hw1, CC, CC);
    tc_gemm<<<gGrid, blk, SMT>>>(ha, CC, hw1, CC, vb, nullptr, hv, CC, 1, 8, 0, 1.f);
    htrans<<<vtGrid, blk>>>(hv, hvt, S, CC);
    tc_gemm<<<qkGrid, blk, SMT>>>(hq, CC, hk, CC, nullptr, nullptr, sc, S, 0, 8, 2, qscale);
    softmax_kernel<<<S, blk>>>(sc, hp);
    tc_gemm<<<gGrid, blk, SMT>>>(hp, S, hvt, S, nullptr, nullptr, ha2, CC, 1, 0, 3, 1.f);
    wcvt<<<w1Grid, blk>>>(pw, hw1, CC, CC);
    tc_gemm<<<gGrid, blk, SMT>>>(ha2, CC, hw1, CC, pb, f1, f2, CC, 0, 8, 0, 1.f);        // f2 = attn out

    // ---- resnet 2 ----
    rmsnorm_kernel<<<S, blk>>>(f2, r2g1, ha, 1);
    wcvt<<<wcGrid, blk>>>(r2w1, hwt, KC, CC);
    tc_gemm<<<gGrid, blk, SMT>>>(ha, CC, hwt, KC, r2b1, nullptr, f1, CC, 0, 27 * 8, 1, 1.f);
    rmsnorm_kernel<<<S, blk>>>(f1, r2g2, ha, 1);
    wcvt<<<wcGrid, blk>>>(r2w2, hwt, KC, CC);
    tc_gemm<<<gGrid, blk, SMT>>>(ha, CC, hwt, KC, r2b2, f2, out, CC, 0, 27 * 8, 1, 1.f);
}